// round 15
// baseline (speedup 1.0000x reference)
#include <cuda_runtime.h>
#include <cuda_fp16.h>
#include <cstdint>

#define TOTAL_PTS 480000
#define NWTILES   15000        // 480000 / 32 points per warp-tile
#define HW        16384        // 128*128
#define NCELLS    65536        // 4 * HW
#define NBINS     65537        // + sentinel bin for invalid points
#define EPSF      1e-5f
#define STR2      72           // K=64  + 8 halfs pad
#define STR3      136          // K=128 + 8 halfs pad

// ---------------- warp MMA helpers (sm_80+; safe on sm_103 base target) -------
__device__ __forceinline__ uint32_t smem_u32(const void* p){
    uint32_t a;
    asm("{ .reg .u64 t; cvta.to.shared.u64 t, %1; cvt.u32.u64 %0, t; }" : "=r"(a) : "l"(p));
    return a;
}
__device__ __forceinline__ void ldsm4(uint32_t r[4], uint32_t addr){
    asm volatile("ldmatrix.sync.aligned.m8n8.x4.shared.b16 {%0,%1,%2,%3}, [%4];"
        : "=r"(r[0]), "=r"(r[1]), "=r"(r[2]), "=r"(r[3]) : "r"(addr));
}
__device__ __forceinline__ void mma16816(float (&d)[4], const uint32_t (&a)[4], uint32_t b0, uint32_t b1){
    asm volatile("mma.sync.aligned.m16n8k16.row.col.f32.f16.f16.f32 "
        "{%0,%1,%2,%3},{%4,%5,%6,%7},{%8,%9},{%0,%1,%2,%3};"
        : "+f"(d[0]), "+f"(d[1]), "+f"(d[2]), "+f"(d[3])
        : "r"(a[0]), "r"(a[1]), "r"(a[2]), "r"(a[3]), "r"(b0), "r"(b1));
}
__device__ __forceinline__ uint32_t pack2(float a, float b){
    __half2 h = __floats2half2_rn(a, b);
    return *reinterpret_cast<uint32_t*>(&h);
}

// ---------------- prepped globals (BN folded; W2 and W3 single fp16) -----
__device__ __align__(16) unsigned short g_w2[128*STR2];
__device__ __align__(16) unsigned short g_w3[128*STR3];
__device__ __align__(16) float g_w1f[256];
__device__ float g_b1f[64], g_b2f[128], g_b3f[128];

// sorted points + sort bookkeeping
__device__ __align__(16) float4 g_spts[TOTAL_PTS];
__device__ int g_pcell[TOTAL_PTS];
__device__ int g_cursor[NBINS];      // after scatter: cursor[c] == end(c)
__device__ int g_hist[NBINS];
__device__ int g_bsum[65];

// materialized per-point features, fp16, row = 128 feats = 64 uint32
__device__ __align__(16) uint32_t g_feat[TOTAL_PTS * 64];

// cell-major max result: scr[cell][feat], 32MB (fully overwritten each call)
__device__ __align__(16) float g_scr[NCELLS * 128];

// ---------------- weight prep ----------------
__global__ void prep_kernel(
    const float* __restrict__ W1, const float* __restrict__ b1,
    const float* __restrict__ g1, const float* __restrict__ be1,
    const float* __restrict__ m1, const float* __restrict__ v1,
    const float* __restrict__ W2, const float* __restrict__ b2,
    const float* __restrict__ g2, const float* __restrict__ be2,
    const float* __restrict__ m2, const float* __restrict__ v2,
    const float* __restrict__ W3, const float* __restrict__ b3,
    const float* __restrict__ g3, const float* __restrict__ be3,
    const float* __restrict__ m3, const float* __restrict__ v3)
{
    int idx = blockIdx.x * blockDim.x + threadIdx.x;
    if (idx < 8192) {                                  // W2 [128 n][64 k]
        int o = idx >> 6, k = idx & 63;
        float s = g2[o] * rsqrtf(v2[o] + EPSF);
        g_w2[o*STR2 + k] = __half_as_ushort(__float2half_rn(W2[idx] * s));
    }
    if (idx < 16384) {                                 // W3 [128 n][128 k]
        int o = idx >> 7, k = idx & 127;
        float s = g3[o] * rsqrtf(v3[o] + EPSF);
        g_w3[o*STR3 + k] = __half_as_ushort(__float2half_rn(W3[idx] * s));
    }
    if (idx < 256) { int o = idx >> 2; g_w1f[idx] = W1[idx] * g1[o] * rsqrtf(v1[o] + EPSF); }
    if (idx < 64)  { float s = g1[idx]*rsqrtf(v1[idx]+EPSF); g_b1f[idx] = (b1[idx]-m1[idx])*s + be1[idx]; }
    if (idx >= 64  && idx < 192) { int i = idx - 64;  float s = g2[i]*rsqrtf(v2[i]+EPSF); g_b2f[i] = (b2[i]-m2[i])*s + be2[i]; }
    if (idx >= 192 && idx < 320) { int i = idx - 192; float s = g3[i]*rsqrtf(v3[i]+EPSF); g_b3f[i] = (b3[i]-m3[i])*s + be3[i]; }
    if (idx < NBINS) g_hist[idx] = 0;
}

// ---------------- counting sort by cell ----------------
__global__ void hist_kernel(const float4* __restrict__ pts)
{
    int p = blockIdx.x * blockDim.x + threadIdx.x;
    if (p >= TOTAL_PTS) return;
    float4 pt = pts[p];
    float xn = (pt.x + 50.0f) / 100.0f;
    float yn = (pt.y + 50.0f) / 100.0f;
    bool valid = (xn >= 0.0f) && (xn <= 1.0f) && (yn >= 0.0f) && (yn <= 1.0f);
    int gx = min(max((int)(xn * 127.0f), 0), 127);
    int gy = min(max((int)(yn * 127.0f), 0), 127);
    int cell = valid ? ((p / 120000) * HW + gy * 128 + gx) : (NBINS - 1);
    g_pcell[p] = cell;
    atomicAdd(&g_hist[cell], 1);
}

__global__ void scanA_kernel()
{
    __shared__ int ws[32];
    int i = blockIdx.x * 1024 + threadIdx.x;
    int v = (i < NBINS) ? g_hist[i] : 0;
    int lane = threadIdx.x & 31, w = threadIdx.x >> 5;
    int inc = v;
    #pragma unroll
    for (int d = 1; d < 32; d <<= 1) {
        int t = __shfl_up_sync(0xffffffffu, inc, d);
        if (lane >= d) inc += t;
    }
    if (lane == 31) ws[w] = inc;
    __syncthreads();
    if (w == 0) {
        int t = ws[lane];
        #pragma unroll
        for (int d = 1; d < 32; d <<= 1) {
            int u = __shfl_up_sync(0xffffffffu, t, d);
            if (lane >= d) t += u;
        }
        ws[lane] = t;
    }
    __syncthreads();
    int woff = (w > 0) ? ws[w - 1] : 0;
    if (i < NBINS) g_cursor[i] = woff + inc - v;
    if (threadIdx.x == 1023) g_bsum[blockIdx.x] = ws[31];
}

__global__ void scanB_kernel()
{
    __shared__ int sh[65];
    int tid = threadIdx.x;
    if (tid < 65) sh[tid] = g_bsum[tid];
    __syncthreads();
    if (tid == 0) { int acc = 0; for (int b = 0; b < 65; b++) { int t = sh[b]; sh[b] = acc; acc += t; } }
    __syncthreads();
    if (tid < 65) g_bsum[tid] = sh[tid];
}

__global__ void scanC_kernel()
{
    int i = blockIdx.x * 1024 + threadIdx.x;
    if (i < NBINS) g_cursor[i] += g_bsum[blockIdx.x];
}

__global__ void scatter_kernel(const float4* __restrict__ pts)
{
    int p = blockIdx.x * blockDim.x + threadIdx.x;
    if (p >= TOTAL_PTS) return;
    int cell = g_pcell[p];
    int pos = atomicAdd(&g_cursor[cell], 1);
    g_spts[pos] = pts[p];
}

// ---------------- smem layout (bytes): ~55.5 KB -> 3 CTAs/SM ----------------
#define OFF_W2   0
#define OFF_W3   (OFF_W2 + 128*STR2*2)      // 18432
#define OFF_B1   (OFF_W3 + 128*STR3*2)      // 53248
#define OFF_B2   (OFF_B1 + 256)
#define OFF_B3   (OFF_B2 + 512)
#define OFF_W1   (OFF_B3 + 512)
#define SMEM_SZ  (OFF_W1 + 1024)            // 55552

__device__ __forceinline__ void l2_pass(const uint32_t (&A)[4][2][4], uint32_t B,
                                        uint32_t boff, float (&acc)[2][4][4])
{
    #pragma unroll
    for (int ks = 0; ks < 4; ks++)
        #pragma unroll
        for (int ntp = 0; ntp < 2; ntp++) {
            uint32_t b[4];
            ldsm4(b, B + boff + ks*32 + ntp*(16*STR2*2));
            mma16816(acc[0][2*ntp],   A[ks][0], b[0], b[1]);
            mma16816(acc[0][2*ntp+1], A[ks][0], b[2], b[3]);
            mma16816(acc[1][2*ntp],   A[ks][1], b[0], b[1]);
            mma16816(acc[1][2*ntp+1], A[ks][1], b[2], b[3]);
        }
}

__device__ __forceinline__ void l3_pass(const uint32_t (&A)[8][2][4], uint32_t B,
                                        uint32_t boff, float (&acc)[2][8][4])
{
    #pragma unroll
    for (int ks = 0; ks < 8; ks++)
        #pragma unroll
        for (int ntp = 0; ntp < 4; ntp++) {
            uint32_t b[4];
            ldsm4(b, B + boff + ks*32 + ntp*(16*STR3*2));
            mma16816(acc[0][2*ntp],   A[ks][0], b[0], b[1]);
            mma16816(acc[0][2*ntp+1], A[ks][0], b[2], b[3]);
            mma16816(acc[1][2*ntp],   A[ks][1], b[0], b[1]);
            mma16816(acc[1][2*ntp+1], A[ks][1], b[2], b[3]);
        }
}

// MLP for all (sorted) points; writes relu'd feats as fp16 rows. NO atomics.
__global__ void __launch_bounds__(128, 3)
enc_kernel()
{
    extern __shared__ __align__(16) char sm[];
    const uint32_t smb = smem_u32(sm);
    const int t = threadIdx.x, lane = t & 31, wid = t >> 5;

    { // stage weights
        uint4* d; const uint4* s;
        d = (uint4*)(sm + OFF_W2); s = (const uint4*)g_w2; for (int i = t; i < 128*STR2*2/16; i += 128) d[i] = s[i];
        d = (uint4*)(sm + OFF_W3); s = (const uint4*)g_w3; for (int i = t; i < 128*STR3*2/16; i += 128) d[i] = s[i];
        float* f;
        f = (float*)(sm + OFF_W1); for (int i = t; i < 256; i += 128) f[i] = g_w1f[i];
        f = (float*)(sm + OFF_B1); if (t < 64)  f[t] = g_b1f[t];
        f = (float*)(sm + OFF_B2); if (t < 128) f[t] = g_b2f[t];
        f = (float*)(sm + OFF_B3); if (t < 128) f[t] = g_b3f[t];
    }
    __syncthreads();

    const float4* sW1 = (const float4*)(sm + OFF_W1);
    const float* sb1 = (const float*)(sm + OFF_B1);
    const float* sb2 = (const float*)(sm + OFF_B2);
    const float* sb3 = (const float*)(sm + OFF_B3);

    const int g = lane >> 2;
    const int cbase = (lane & 3) * 2;
    const uint32_t boff2 = (uint32_t)(((lane & 7) + ((lane >> 4) << 3)) * STR2) * 2 + (lane & 8) * 2;
    const uint32_t boff3 = (uint32_t)(((lane & 7) + ((lane >> 4) << 3)) * STR3) * 2 + (lane & 8) * 2;

    const int gwarp = blockIdx.x * 4 + wid;
    const int nwarps = gridDim.x * 4;

    for (int wt = gwarp; wt < NWTILES; wt += nwarps) {
        const int p = wt * 32 + lane;
        float4 pt = g_spts[p];

        // points for the 4 rows this lane's accumulators cover (rows g+8q)
        float4 ptq[4];
        #pragma unroll
        for (int q = 0; q < 4; q++) {
            int src = g + 8 * q;
            ptq[q].x = __shfl_sync(0xffffffffu, pt.x, src);
            ptq[q].y = __shfl_sync(0xffffffffu, pt.y, src);
            ptq[q].z = __shfl_sync(0xffffffffu, pt.z, src);
            ptq[q].w = __shfl_sync(0xffffffffu, pt.w, src);
        }

        // ---- layer 1: build A1 fp16 fragments directly in registers ----
        uint32_t a1[4][2][4];
        #pragma unroll
        for (int ks = 0; ks < 4; ks++)
            #pragma unroll
            for (int off8 = 0; off8 < 2; off8++) {
                int k0 = ks * 16 + off8 * 8 + cbase;
                float4 w0 = sW1[k0], w1 = sW1[k0 + 1];
                float bb0 = sb1[k0], bb1 = sb1[k0 + 1];
                #pragma unroll
                for (int mb = 0; mb < 2; mb++)
                    #pragma unroll
                    for (int rh = 0; rh < 2; rh++) {
                        float4 q = ptq[2 * mb + rh];
                        float v0 = bb0, v1 = bb1;
                        v0 = fmaf(q.x, w0.x, v0); v0 = fmaf(q.y, w0.y, v0);
                        v0 = fmaf(q.z, w0.z, v0); v0 = fmaf(q.w, w0.w, v0);
                        v1 = fmaf(q.x, w1.x, v1); v1 = fmaf(q.y, w1.y, v1);
                        v1 = fmaf(q.z, w1.z, v1); v1 = fmaf(q.w, w1.w, v1);
                        a1[ks][mb][off8 * 2 + rh] = pack2(fmaxf(v0, 0.0f), fmaxf(v1, 0.0f));
                    }
            }

        // ---- layer 2 + epilogue, ONE 32-col chunk at a time ----
        uint32_t a2[8][2][4];
        #pragma unroll
        for (int nc = 0; nc < 4; nc++) {
            float acc2[2][4][4];
            #pragma unroll
            for (int mb = 0; mb < 2; mb++)
                #pragma unroll
                for (int nt = 0; nt < 4; nt++)
                    #pragma unroll
                    for (int r = 0; r < 4; r++) acc2[mb][nt][r] = 0.0f;

            l2_pass(a1, smb + OFF_W2 + nc * (32 * STR2 * 2), boff2, acc2);

            #pragma unroll
            for (int sub = 0; sub < 2; sub++) {
                const int ks3 = nc * 2 + sub;
                const int ntA = sub * 2;
                const int colA = ks3 * 16 + cbase;
                float bA0 = sb2[colA], bA1 = sb2[colA + 1];
                float bB0 = sb2[colA + 8], bB1 = sb2[colA + 9];
                #pragma unroll
                for (int mb = 0; mb < 2; mb++) {
                    a2[ks3][mb][0] = pack2(fmaxf(acc2[mb][ntA][0] + bA0, 0.0f),
                                           fmaxf(acc2[mb][ntA][1] + bA1, 0.0f));
                    a2[ks3][mb][1] = pack2(fmaxf(acc2[mb][ntA][2] + bA0, 0.0f),
                                           fmaxf(acc2[mb][ntA][3] + bA1, 0.0f));
                    a2[ks3][mb][2] = pack2(fmaxf(acc2[mb][ntA + 1][0] + bB0, 0.0f),
                                           fmaxf(acc2[mb][ntA + 1][1] + bB1, 0.0f));
                    a2[ks3][mb][3] = pack2(fmaxf(acc2[mb][ntA + 1][2] + bB0, 0.0f),
                                           fmaxf(acc2[mb][ntA + 1][3] + bB1, 0.0f));
                }
            }
        }

        // ---- layer 3 + relu + fp16 store of feature rows (no atomics) ----
        #pragma unroll
        for (int nh3 = 0; nh3 < 2; nh3++) {
            float acc3[2][8][4];
            #pragma unroll
            for (int mb = 0; mb < 2; mb++)
                #pragma unroll
                for (int nt = 0; nt < 8; nt++)
                    #pragma unroll
                    for (int r = 0; r < 4; r++) acc3[mb][nt][r] = 0.0f;

            l3_pass(a2, smb + OFF_W3 + nh3 * (64 * STR3 * 2), boff3, acc3);

            #pragma unroll
            for (int mb = 0; mb < 2; mb++)
                #pragma unroll
                for (int rp = 0; rp < 2; rp++) {
                    int row = wt * 32 + 16 * mb + 8 * rp + g;
                    uint32_t* orow = g_feat + row * 64 + nh3 * 32;
                    #pragma unroll
                    for (int nt = 0; nt < 8; nt++) {
                        int col = nt * 8 + cbase;            // local to this half
                        float v0 = fmaxf(acc3[mb][nt][2 * rp]     + sb3[nh3 * 64 + col],     0.0f);
                        float v1 = fmaxf(acc3[mb][nt][2 * rp + 1] + sb3[nh3 * 64 + col + 1], 0.0f);
                        orow[col >> 1] = pack2(v0, v1);
                    }
                }
        }
    }
}

// warp-per-cell max reduction over sorted feature rows -> cell-major g_scr.
// Writes EVERY cell (zeros for empty) -> no zero-init kernel needed.
__global__ void __launch_bounds__(256)
reduce_kernel()
{
    int w = blockIdx.x * 8 + (threadIdx.x >> 5);     // cell id, grid 8192
    int lane = threadIdx.x & 31;
    int s = (w == 0) ? 0 : g_cursor[w - 1];
    int e = g_cursor[w];
    float m0 = 0.f, m1 = 0.f, m2 = 0.f, m3 = 0.f;
    for (int pos = s; pos < e; pos++) {
        uint32_t u0 = g_feat[pos * 64 + lane];
        uint32_t u1 = g_feat[pos * 64 + 32 + lane];
        __half2 h0 = *reinterpret_cast<__half2*>(&u0);
        __half2 h1 = *reinterpret_cast<__half2*>(&u1);
        m0 = fmaxf(m0, __low2float(h0));  m1 = fmaxf(m1, __high2float(h0));
        m2 = fmaxf(m2, __low2float(h1));  m3 = fmaxf(m3, __high2float(h1));
    }
    float* orow = g_scr + (size_t)w * 128;
    *(float2*)(orow + 2 * lane)      = make_float2(m0, m1);
    *(float2*)(orow + 64 + 2 * lane) = make_float2(m2, m3);
}

// transpose scratch (B, HW, 128) -> out (B, 128, HW); float4 both sides (R11).
__global__ void transpose_kernel(float* __restrict__ out)
{
    __shared__ float tile[32][33];
    const float* scr = g_scr;
    int b  = blockIdx.z;
    int f0 = blockIdx.y * 32;
    int c0 = blockIdx.x * 32;
    int tid = threadIdx.x;                 // 256 threads
    int cr = tid >> 3, f4 = tid & 7;
    float4 v = *(const float4*)(scr + ((size_t)(b * HW + c0 + cr)) * 128 + f0 + f4 * 4);
    tile[cr][f4 * 4 + 0] = v.x; tile[cr][f4 * 4 + 1] = v.y;
    tile[cr][f4 * 4 + 2] = v.z; tile[cr][f4 * 4 + 3] = v.w;
    __syncthreads();
    int fr = tid >> 3, c4 = tid & 7;
    float4 o;
    o.x = tile[c4 * 4 + 0][fr]; o.y = tile[c4 * 4 + 1][fr];
    o.z = tile[c4 * 4 + 2][fr]; o.w = tile[c4 * 4 + 3][fr];
    *(float4*)(out + ((size_t)(b * 128 + f0 + fr)) * HW + c0 + c4 * 4) = o;
}

extern "C" void kernel_launch(void* const* d_in, const int* in_sizes, int n_in,
                              void* d_out, int out_size)
{
    const float* points = (const float*)d_in[0];
    const float* W1  = (const float*)d_in[1];
    const float* b1  = (const float*)d_in[2];
    const float* g1  = (const float*)d_in[3];
    const float* be1 = (const float*)d_in[4];
    const float* m1  = (const float*)d_in[5];
    const float* v1  = (const float*)d_in[6];
    const float* W2  = (const float*)d_in[7];
    const float* b2  = (const float*)d_in[8];
    const float* g2  = (const float*)d_in[9];
    const float* be2 = (const float*)d_in[10];
    const float* m2  = (const float*)d_in[11];
    const float* v2  = (const float*)d_in[12];
    const float* W3  = (const float*)d_in[13];
    const float* b3  = (const float*)d_in[14];
    const float* g3  = (const float*)d_in[15];
    const float* be3 = (const float*)d_in[16];
    const float* m3  = (const float*)d_in[17];
    const float* v3  = (const float*)d_in[18];

    prep_kernel<<<260, 256>>>(W1, b1, g1, be1, m1, v1,
                              W2, b2, g2, be2, m2, v2,
                              W3, b3, g3, be3, m3, v3);

    hist_kernel<<<(TOTAL_PTS + 255) / 256, 256>>>((const float4*)points);
    scanA_kernel<<<65, 1024>>>();
    scanB_kernel<<<1, 128>>>();
    scanC_kernel<<<65, 1024>>>();
    scatter_kernel<<<(TOTAL_PTS + 255) / 256, 256>>>((const float4*)points);

    cudaFuncSetAttribute(enc_kernel,
                         cudaFuncAttributeMaxDynamicSharedMemorySize, SMEM_SZ);
    enc_kernel<<<444, 128, SMEM_SZ>>>();

    reduce_kernel<<<NCELLS / 8, 256>>>();

    transpose_kernel<<<dim3(512, 4, 4), dim3(256)>>>((float*)d_out);
}

// round 16
// speedup vs baseline: 2.1477x; 2.1477x over previous
#include <cuda_runtime.h>
#include <cuda_fp16.h>
#include <cstdint>

#define TOTAL_PTS 480000
#define NWTILES   15000        // 480000 / 32 points per warp-tile
#define HW        16384        // 128*128
#define EPSF      1e-5f
#define STR2      72           // K=64  + 8 halfs pad
#define STR3      136          // K=128 + 8 halfs pad

// ---------------- warp MMA helpers (sm_80+; safe on sm_103 base target) -------
__device__ __forceinline__ uint32_t smem_u32(const void* p){
    uint32_t a;
    asm("{ .reg .u64 t; cvta.to.shared.u64 t, %1; cvt.u32.u64 %0, t; }" : "=r"(a) : "l"(p));
    return a;
}
__device__ __forceinline__ void ldsm4(uint32_t r[4], uint32_t addr){
    asm volatile("ldmatrix.sync.aligned.m8n8.x4.shared.b16 {%0,%1,%2,%3}, [%4];"
        : "=r"(r[0]), "=r"(r[1]), "=r"(r[2]), "=r"(r[3]) : "r"(addr));
}
__device__ __forceinline__ void mma16816(float (&d)[4], const uint32_t (&a)[4], uint32_t b0, uint32_t b1){
    asm volatile("mma.sync.aligned.m16n8k16.row.col.f32.f16.f16.f32 "
        "{%0,%1,%2,%3},{%4,%5,%6,%7},{%8,%9},{%0,%1,%2,%3};"
        : "+f"(d[0]), "+f"(d[1]), "+f"(d[2]), "+f"(d[3])
        : "r"(a[0]), "r"(a[1]), "r"(a[2]), "r"(a[3]), "r"(b0), "r"(b1));
}
__device__ __forceinline__ uint32_t pack2(float a, float b){
    __half2 h = __floats2half2_rn(a, b);
    return *reinterpret_cast<uint32_t*>(&h);
}

// ---------------- prepped globals (BN folded; W2 and W3 single fp16) -----
__device__ __align__(16) unsigned short g_w2[128*STR2];
__device__ __align__(16) unsigned short g_w3[128*STR3];
__device__ __align__(16) float g_w1f[256];
__device__ float g_b1f[64], g_b2f[128], g_b3f[128];

// cell-major scatter scratch: scr[b][cell][feat], 32MB
__device__ __align__(16) int g_scr[4 * HW * 128];

// slim weight-prep: one element per thread, no loops (latency-bound work)
__global__ void prep_kernel(
    const float* __restrict__ W1, const float* __restrict__ b1,
    const float* __restrict__ g1, const float* __restrict__ be1,
    const float* __restrict__ m1, const float* __restrict__ v1,
    const float* __restrict__ W2, const float* __restrict__ b2,
    const float* __restrict__ g2, const float* __restrict__ be2,
    const float* __restrict__ m2, const float* __restrict__ v2,
    const float* __restrict__ W3, const float* __restrict__ b3,
    const float* __restrict__ g3, const float* __restrict__ be3,
    const float* __restrict__ m3, const float* __restrict__ v3)
{
    int idx = blockIdx.x * blockDim.x + threadIdx.x;

    if (idx < 8192) {                                  // W2 [128 n][64 k], single fp16
        int o = idx >> 6, k = idx & 63;
        float s = g2[o] * rsqrtf(v2[o] + EPSF);
        g_w2[o*STR2 + k] = __half_as_ushort(__float2half_rn(W2[idx] * s));
    }
    if (idx < 16384) {                                 // W3 [128 n][128 k], single fp16
        int o = idx >> 7, k = idx & 127;
        float s = g3[o] * rsqrtf(v3[o] + EPSF);
        g_w3[o*STR3 + k] = __half_as_ushort(__float2half_rn(W3[idx] * s));
    }
    if (idx < 256) { int o = idx >> 2; g_w1f[idx] = W1[idx] * g1[o] * rsqrtf(v1[o] + EPSF); }
    if (idx < 64)  { float s = g1[idx]*rsqrtf(v1[idx]+EPSF); g_b1f[idx] = (b1[idx]-m1[idx])*s + be1[idx]; }
    if (idx >= 64  && idx < 192) { int i = idx - 64;  float s = g2[i]*rsqrtf(v2[i]+EPSF); g_b2f[i] = (b2[i]-m2[i])*s + be2[i]; }
    if (idx >= 192 && idx < 320) { int i = idx - 192; float s = g3[i]*rsqrtf(v3[i]+EPSF); g_b3f[i] = (b3[i]-m3[i])*s + be3[i]; }
}

// ---------------- smem layout (bytes): ~55.5 KB -> 3 CTAs/SM ----------------
#define OFF_W2   0
#define OFF_W3   (OFF_W2 + 128*STR2*2)      // 18432
#define OFF_B1   (OFF_W3 + 128*STR3*2)      // 53248
#define OFF_B2   (OFF_B1 + 256)
#define OFF_B3   (OFF_B2 + 512)
#define OFF_W1   (OFF_B3 + 512)
#define SMEM_SZ  (OFF_W1 + 1024)            // 55552

// layer-2 GEMM pass over ONE 32-col chunk, M=32: acc[mb][nt][4] (32 regs).
__device__ __forceinline__ void l2_pass(const uint32_t (&A)[4][2][4], uint32_t B,
                                        uint32_t boff, float (&acc)[2][4][4])
{
    #pragma unroll
    for (int ks = 0; ks < 4; ks++)
        #pragma unroll
        for (int ntp = 0; ntp < 2; ntp++) {
            uint32_t b[4];
            ldsm4(b, B + boff + ks*32 + ntp*(16*STR2*2));
            mma16816(acc[0][2*ntp],   A[ks][0], b[0], b[1]);
            mma16816(acc[0][2*ntp+1], A[ks][0], b[2], b[3]);
            mma16816(acc[1][2*ntp],   A[ks][1], b[0], b[1]);
            mma16816(acc[1][2*ntp+1], A[ks][1], b[2], b[3]);
        }
}

// layer-3 GEMM pass for one 64-col n-half, M=32, single fp16 weights.
__device__ __forceinline__ void l3_pass(const uint32_t (&A)[8][2][4], uint32_t B,
                                        uint32_t boff, float (&acc)[2][8][4])
{
    #pragma unroll
    for (int ks = 0; ks < 8; ks++)
        #pragma unroll
        for (int ntp = 0; ntp < 4; ntp++) {
            uint32_t b[4];
            ldsm4(b, B + boff + ks*32 + ntp*(16*STR3*2));
            mma16816(acc[0][2*ntp],   A[ks][0], b[0], b[1]);
            mma16816(acc[0][2*ntp+1], A[ks][0], b[2], b[3]);
            mma16816(acc[1][2*ntp],   A[ks][1], b[0], b[1]);
            mma16816(acc[1][2*ntp+1], A[ks][1], b[2], b[3]);
        }
}

__global__ void __launch_bounds__(128, 3)
enc_kernel(const float4* __restrict__ pts)
{
    extern __shared__ __align__(16) char sm[];
    const uint32_t smb = smem_u32(sm);
    const int t = threadIdx.x, lane = t & 31, wid = t >> 5;

    { // stage weights
        uint4* d; const uint4* s;
        d = (uint4*)(sm + OFF_W2); s = (const uint4*)g_w2; for (int i = t; i < 128*STR2*2/16; i += 128) d[i] = s[i];
        d = (uint4*)(sm + OFF_W3); s = (const uint4*)g_w3; for (int i = t; i < 128*STR3*2/16; i += 128) d[i] = s[i];
        float* f;
        f = (float*)(sm + OFF_W1); for (int i = t; i < 256; i += 128) f[i] = g_w1f[i];
        f = (float*)(sm + OFF_B1); if (t < 64)  f[t] = g_b1f[t];
        f = (float*)(sm + OFF_B2); if (t < 128) f[t] = g_b2f[t];
        f = (float*)(sm + OFF_B3); if (t < 128) f[t] = g_b3f[t];
    }
    __syncthreads();

    const float4* sW1 = (const float4*)(sm + OFF_W1);
    const float* sb1 = (const float*)(sm + OFF_B1);
    const float* sb2 = (const float*)(sm + OFF_B2);
    const float* sb3 = (const float*)(sm + OFF_B3);

    const int g = lane >> 2;
    const int cbase = (lane & 3) * 2;
    const uint32_t boff2 = (uint32_t)(((lane & 7) + ((lane >> 4) << 3)) * STR2) * 2 + (lane & 8) * 2;
    const uint32_t boff3 = (uint32_t)(((lane & 7) + ((lane >> 4) << 3)) * STR3) * 2 + (lane & 8) * 2;

    const int gwarp = blockIdx.x * 4 + wid;
    const int nwarps = gridDim.x * 4;

    for (int wt = gwarp; wt < NWTILES; wt += nwarps) {
        const int p = wt * 32 + lane;
        float4 pt = pts[p];

        float xn = (pt.x + 50.0f) / 100.0f;
        float yn = (pt.y + 50.0f) / 100.0f;
        bool valid = (xn >= 0.0f) && (xn <= 1.0f) && (yn >= 0.0f) && (yn <= 1.0f);
        int gx = min(max((int)(xn * 127.0f), 0), 127);
        int gy = min(max((int)(yn * 127.0f), 0), 127);
        // cell-major scratch base: (b*HW + cell) * 128
        int cellb = valid ? (((p / 120000) * HW + gy * 128 + gx) << 7) : -1;

        // bases + points for the 4 rows this lane's accumulators cover (rows g+8q)
        int cell_r[4];
        float4 ptq[4];
        #pragma unroll
        for (int q = 0; q < 4; q++) {
            int src = g + 8 * q;
            cell_r[q] = __shfl_sync(0xffffffffu, cellb, src);
            ptq[q].x = __shfl_sync(0xffffffffu, pt.x, src);
            ptq[q].y = __shfl_sync(0xffffffffu, pt.y, src);
            ptq[q].z = __shfl_sync(0xffffffffu, pt.z, src);
            ptq[q].w = __shfl_sync(0xffffffffu, pt.w, src);
        }

        // ---- layer 1: build A1 fp16 fragments directly in registers ----
        uint32_t a1[4][2][4];
        #pragma unroll
        for (int ks = 0; ks < 4; ks++)
            #pragma unroll
            for (int off8 = 0; off8 < 2; off8++) {
                int k0 = ks * 16 + off8 * 8 + cbase;
                float4 w0 = sW1[k0], w1 = sW1[k0 + 1];
                float bb0 = sb1[k0], bb1 = sb1[k0 + 1];
                #pragma unroll
                for (int mb = 0; mb < 2; mb++)
                    #pragma unroll
                    for (int rh = 0; rh < 2; rh++) {
                        float4 q = ptq[2 * mb + rh];
                        float v0 = bb0, v1 = bb1;
                        v0 = fmaf(q.x, w0.x, v0); v0 = fmaf(q.y, w0.y, v0);
                        v0 = fmaf(q.z, w0.z, v0); v0 = fmaf(q.w, w0.w, v0);
                        v1 = fmaf(q.x, w1.x, v1); v1 = fmaf(q.y, w1.y, v1);
                        v1 = fmaf(q.z, w1.z, v1); v1 = fmaf(q.w, w1.w, v1);
                        a1[ks][mb][off8 * 2 + rh] = pack2(fmaxf(v0, 0.0f), fmaxf(v1, 0.0f));
                    }
            }

        // ---- layer 2 + epilogue, ONE 32-col chunk at a time (acc2 = 32 regs) ----
        uint32_t a2[8][2][4];
        #pragma unroll
        for (int nc = 0; nc < 4; nc++) {
            float acc2[2][4][4];
            #pragma unroll
            for (int mb = 0; mb < 2; mb++)
                #pragma unroll
                for (int nt = 0; nt < 4; nt++)
                    #pragma unroll
                    for (int r = 0; r < 4; r++) acc2[mb][nt][r] = 0.0f;

            l2_pass(a1, smb + OFF_W2 + nc * (32 * STR2 * 2), boff2, acc2);

            // bias+relu, convert C frags -> layer-3 A frags (ks3 = nc*2 + sub)
            #pragma unroll
            for (int sub = 0; sub < 2; sub++) {
                const int ks3 = nc * 2 + sub;
                const int ntA = sub * 2;
                const int colA = ks3 * 16 + cbase;
                float bA0 = sb2[colA], bA1 = sb2[colA + 1];
                float bB0 = sb2[colA + 8], bB1 = sb2[colA + 9];
                #pragma unroll
                for (int mb = 0; mb < 2; mb++) {
                    a2[ks3][mb][0] = pack2(fmaxf(acc2[mb][ntA][0] + bA0, 0.0f),
                                           fmaxf(acc2[mb][ntA][1] + bA1, 0.0f));
                    a2[ks3][mb][1] = pack2(fmaxf(acc2[mb][ntA][2] + bA0, 0.0f),
                                           fmaxf(acc2[mb][ntA][3] + bA1, 0.0f));
                    a2[ks3][mb][2] = pack2(fmaxf(acc2[mb][ntA + 1][0] + bB0, 0.0f),
                                           fmaxf(acc2[mb][ntA + 1][1] + bB1, 0.0f));
                    a2[ks3][mb][3] = pack2(fmaxf(acc2[mb][ntA + 1][2] + bB0, 0.0f),
                                           fmaxf(acc2[mb][ntA + 1][3] + bB1, 0.0f));
                }
            }
        }

        // ---- layer 3: [32x128] x [128x128]^T + contiguous scatter-max ----
        #pragma unroll
        for (int nh3 = 0; nh3 < 2; nh3++) {
            float acc3[2][8][4];
            #pragma unroll
            for (int mb = 0; mb < 2; mb++)
                #pragma unroll
                for (int nt = 0; nt < 8; nt++)
                    #pragma unroll
                    for (int r = 0; r < 4; r++) acc3[mb][nt][r] = 0.0f;

            l3_pass(a2, smb + OFF_W3 + nh3 * (64 * STR3 * 2), boff3, acc3);

            // scatter: relu folded into the >0 skip (scratch is zero at entry)
            #pragma unroll
            for (int mb = 0; mb < 2; mb++)
                #pragma unroll
                for (int rp = 0; rp < 2; rp++) {
                    int cb = cell_r[mb * 2 + rp];
                    if (cb >= 0) {
                        int* orow = g_scr + cb;
                        #pragma unroll
                        for (int nt = 0; nt < 8; nt++) {
                            int col = nh3 * 64 + nt * 8 + cbase;
                            float v0 = acc3[mb][nt][2 * rp]     + sb3[col];
                            float v1 = acc3[mb][nt][2 * rp + 1] + sb3[col + 1];
                            if (v0 > 0.0f) atomicMax(orow + col,     __float_as_int(v0));
                            if (v1 > 0.0f) atomicMax(orow + col + 1, __float_as_int(v1));
                        }
                    }
                }
        }
    }
}

// transpose scratch (B, HW, 128) -> out (B, 128, HW); float4 both sides.
__global__ void transpose_kernel(float* __restrict__ out)
{
    __shared__ float tile[32][33];
    const float* scr = (const float*)g_scr;
    int b  = blockIdx.z;
    int f0 = blockIdx.y * 32;
    int c0 = blockIdx.x * 32;
    int tid = threadIdx.x;                 // 256 threads
    int cr = tid >> 3, f4 = tid & 7;
    float4 v = *(const float4*)(scr + ((size_t)(b * HW + c0 + cr)) * 128 + f0 + f4 * 4);
    tile[cr][f4 * 4 + 0] = v.x; tile[cr][f4 * 4 + 1] = v.y;
    tile[cr][f4 * 4 + 2] = v.z; tile[cr][f4 * 4 + 3] = v.w;
    __syncthreads();
    int fr = tid >> 3, c4 = tid & 7;
    float4 o;
    o.x = tile[c4 * 4 + 0][fr]; o.y = tile[c4 * 4 + 1][fr];
    o.z = tile[c4 * 4 + 2][fr]; o.w = tile[c4 * 4 + 3][fr];
    *(float4*)(out + ((size_t)(b * 128 + f0 + fr)) * HW + c0 + c4 * 4) = o;
}

extern "C" void kernel_launch(void* const* d_in, const int* in_sizes, int n_in,
                              void* d_out, int out_size)
{
    const float* points = (const float*)d_in[0];
    const float* W1  = (const float*)d_in[1];
    const float* b1  = (const float*)d_in[2];
    const float* g1  = (const float*)d_in[3];
    const float* be1 = (const float*)d_in[4];
    const float* m1  = (const float*)d_in[5];
    const float* v1  = (const float*)d_in[6];
    const float* W2  = (const float*)d_in[7];
    const float* b2  = (const float*)d_in[8];
    const float* g2  = (const float*)d_in[9];
    const float* be2 = (const float*)d_in[10];
    const float* m2  = (const float*)d_in[11];
    const float* v2  = (const float*)d_in[12];
    const float* W3  = (const float*)d_in[13];
    const float* b3  = (const float*)d_in[14];
    const float* g3  = (const float*)d_in[15];
    const float* be3 = (const float*)d_in[16];
    const float* m3  = (const float*)d_in[17];
    const float* v3  = (const float*)d_in[18];

    // zero + L2-warm scratch via driver memset (graph-capturable, no alloc)
    void* scr_ptr = nullptr;
    cudaGetSymbolAddress(&scr_ptr, g_scr);
    cudaMemsetAsync(scr_ptr, 0, sizeof(g_scr), 0);

    prep_kernel<<<128, 256>>>(W1, b1, g1, be1, m1, v1,
                              W2, b2, g2, be2, m2, v2,
                              W3, b3, g3, be3, m3, v3);

    cudaFuncSetAttribute(enc_kernel,
                         cudaFuncAttributeMaxDynamicSharedMemorySize, SMEM_SZ);
    enc_kernel<<<444, 128, SMEM_SZ>>>((const float4*)points);

    transpose_kernel<<<dim3(512, 4, 4), dim3(256)>>>((float*)d_out);
}

// round 17
// speedup vs baseline: 2.2128x; 1.0303x over previous
#include <cuda_runtime.h>
#include <cuda_fp16.h>
#include <cstdint>

#define TOTAL_PTS 480000
#define NWTILES   15000        // 480000 / 32 points per warp-tile
#define HW        16384        // 128*128
#define EPSF      1e-5f
#define STR2      72           // K=64  + 8 halfs pad
#define STR3      136          // K=128 + 8 halfs pad

// ---------------- warp MMA helpers (sm_80+; safe on sm_103 base target) -------
__device__ __forceinline__ uint32_t smem_u32(const void* p){
    uint32_t a;
    asm("{ .reg .u64 t; cvta.to.shared.u64 t, %1; cvt.u32.u64 %0, t; }" : "=r"(a) : "l"(p));
    return a;
}
__device__ __forceinline__ void ldsm4(uint32_t r[4], uint32_t addr){
    asm volatile("ldmatrix.sync.aligned.m8n8.x4.shared.b16 {%0,%1,%2,%3}, [%4];"
        : "=r"(r[0]), "=r"(r[1]), "=r"(r[2]), "=r"(r[3]) : "r"(addr));
}
__device__ __forceinline__ void mma16816(float (&d)[4], const uint32_t (&a)[4], uint32_t b0, uint32_t b1){
    asm volatile("mma.sync.aligned.m16n8k16.row.col.f32.f16.f16.f32 "
        "{%0,%1,%2,%3},{%4,%5,%6,%7},{%8,%9},{%0,%1,%2,%3};"
        : "+f"(d[0]), "+f"(d[1]), "+f"(d[2]), "+f"(d[3])
        : "r"(a[0]), "r"(a[1]), "r"(a[2]), "r"(a[3]), "r"(b0), "r"(b1));
}
__device__ __forceinline__ uint32_t pack2(float a, float b){
    __half2 h = __floats2half2_rn(a, b);
    return *reinterpret_cast<uint32_t*>(&h);
}

// ---------------- prepped globals (BN folded; W2 and W3 single fp16) -----
__device__ __align__(16) unsigned short g_w2[128*STR2];
__device__ __align__(16) unsigned short g_w3[128*STR3];
__device__ __align__(16) float g_w1f[256];
__device__ float g_b1f[64], g_b2f[128], g_b3f[128];

// cell-major scatter scratch: scr[b][cell][feat], 32MB
__device__ __align__(16) int g_scr[4 * HW * 128];

// merged zero + weight-prep kernel (R13): zeroing (and L2-warming) the scratch
// is the bulk; the tiny BN-fold work rides along on the low indices' threads.
__global__ void init_kernel(
    const float* __restrict__ W1, const float* __restrict__ b1,
    const float* __restrict__ g1, const float* __restrict__ be1,
    const float* __restrict__ m1, const float* __restrict__ v1,
    const float* __restrict__ W2, const float* __restrict__ b2,
    const float* __restrict__ g2, const float* __restrict__ be2,
    const float* __restrict__ m2, const float* __restrict__ v2,
    const float* __restrict__ W3, const float* __restrict__ b3,
    const float* __restrict__ g3, const float* __restrict__ be3,
    const float* __restrict__ m3, const float* __restrict__ v3)
{
    int idx = blockIdx.x * blockDim.x + threadIdx.x;
    int nthr = gridDim.x * blockDim.x;

    // ---- weight prep (bounds << nthr; each thread does at most 1 element) ----
    if (idx < 8192) {                                  // W2 [128 n][64 k], single fp16
        int o = idx >> 6, k = idx & 63;
        float s = g2[o] * rsqrtf(v2[o] + EPSF);
        g_w2[o*STR2 + k] = __half_as_ushort(__float2half_rn(W2[idx] * s));
    }
    if (idx < 16384) {                                 // W3 [128 n][128 k], single fp16
        int o = idx >> 7, k = idx & 127;
        float s = g3[o] * rsqrtf(v3[o] + EPSF);
        g_w3[o*STR3 + k] = __half_as_ushort(__float2half_rn(W3[idx] * s));
    }
    if (idx < 256) { int o = idx >> 2; g_w1f[idx] = W1[idx] * g1[o] * rsqrtf(v1[o] + EPSF); }
    if (idx < 64)  { float s = g1[idx]*rsqrtf(v1[idx]+EPSF); g_b1f[idx] = (b1[idx]-m1[idx])*s + be1[idx]; }
    if (idx >= 64  && idx < 192) { int i = idx - 64;  float s = g2[i]*rsqrtf(v2[i]+EPSF); g_b2f[i] = (b2[i]-m2[i])*s + be2[i]; }
    if (idx >= 192 && idx < 320) { int i = idx - 192; float s = g3[i]*rsqrtf(v3[i]+EPSF); g_b3f[i] = (b3[i]-m3[i])*s + be3[i]; }

    // ---- zero + L2-warm the 32MB scatter scratch ----
    int4* p = (int4*)g_scr;
    const int n = (4 * HW * 128) / 4;
    for (int i = idx; i < n; i += nthr)
        p[i] = make_int4(0, 0, 0, 0);
}

// ---------------- smem layout (bytes): ~55.5 KB -> 3 CTAs/SM ----------------
#define OFF_W2   0
#define OFF_W3   (OFF_W2 + 128*STR2*2)      // 18432
#define OFF_B1   (OFF_W3 + 128*STR3*2)      // 53248
#define OFF_B2   (OFF_B1 + 256)
#define OFF_B3   (OFF_B2 + 512)
#define OFF_W1   (OFF_B3 + 512)
#define SMEM_SZ  (OFF_W1 + 1024)            // 55552

// layer-2 GEMM pass over ONE 32-col chunk, M=32: acc[mb][nt][4] (32 regs).
__device__ __forceinline__ void l2_pass(const uint32_t (&A)[4][2][4], uint32_t B,
                                        uint32_t boff, float (&acc)[2][4][4])
{
    #pragma unroll
    for (int ks = 0; ks < 4; ks++)
        #pragma unroll
        for (int ntp = 0; ntp < 2; ntp++) {
            uint32_t b[4];
            ldsm4(b, B + boff + ks*32 + ntp*(16*STR2*2));
            mma16816(acc[0][2*ntp],   A[ks][0], b[0], b[1]);
            mma16816(acc[0][2*ntp+1], A[ks][0], b[2], b[3]);
            mma16816(acc[1][2*ntp],   A[ks][1], b[0], b[1]);
            mma16816(acc[1][2*ntp+1], A[ks][1], b[2], b[3]);
        }
}

// layer-3 GEMM pass for one 64-col n-half, M=32, single fp16 weights.
__device__ __forceinline__ void l3_pass(const uint32_t (&A)[8][2][4], uint32_t B,
                                        uint32_t boff, float (&acc)[2][8][4])
{
    #pragma unroll
    for (int ks = 0; ks < 8; ks++)
        #pragma unroll
        for (int ntp = 0; ntp < 4; ntp++) {
            uint32_t b[4];
            ldsm4(b, B + boff + ks*32 + ntp*(16*STR3*2));
            mma16816(acc[0][2*ntp],   A[ks][0], b[0], b[1]);
            mma16816(acc[0][2*ntp+1], A[ks][0], b[2], b[3]);
            mma16816(acc[1][2*ntp],   A[ks][1], b[0], b[1]);
            mma16816(acc[1][2*ntp+1], A[ks][1], b[2], b[3]);
        }
}

__global__ void __launch_bounds__(128, 3)
enc_kernel(const float4* __restrict__ pts)
{
    extern __shared__ __align__(16) char sm[];
    const uint32_t smb = smem_u32(sm);
    const int t = threadIdx.x, lane = t & 31, wid = t >> 5;

    { // stage weights
        uint4* d; const uint4* s;
        d = (uint4*)(sm + OFF_W2); s = (const uint4*)g_w2; for (int i = t; i < 128*STR2*2/16; i += 128) d[i] = s[i];
        d = (uint4*)(sm + OFF_W3); s = (const uint4*)g_w3; for (int i = t; i < 128*STR3*2/16; i += 128) d[i] = s[i];
        float* f;
        f = (float*)(sm + OFF_W1); for (int i = t; i < 256; i += 128) f[i] = g_w1f[i];
        f = (float*)(sm + OFF_B1); if (t < 64)  f[t] = g_b1f[t];
        f = (float*)(sm + OFF_B2); if (t < 128) f[t] = g_b2f[t];
        f = (float*)(sm + OFF_B3); if (t < 128) f[t] = g_b3f[t];
    }
    __syncthreads();

    const float4* sW1 = (const float4*)(sm + OFF_W1);
    const float* sb1 = (const float*)(sm + OFF_B1);
    const float* sb2 = (const float*)(sm + OFF_B2);
    const float* sb3 = (const float*)(sm + OFF_B3);

    const int g = lane >> 2;
    const int cbase = (lane & 3) * 2;
    const uint32_t boff2 = (uint32_t)(((lane & 7) + ((lane >> 4) << 3)) * STR2) * 2 + (lane & 8) * 2;
    const uint32_t boff3 = (uint32_t)(((lane & 7) + ((lane >> 4) << 3)) * STR3) * 2 + (lane & 8) * 2;

    const int gwarp = blockIdx.x * 4 + wid;
    const int nwarps = gridDim.x * 4;

    for (int wt = gwarp; wt < NWTILES; wt += nwarps) {
        const int p = wt * 32 + lane;
        float4 pt = pts[p];

        float xn = (pt.x + 50.0f) / 100.0f;
        float yn = (pt.y + 50.0f) / 100.0f;
        bool valid = (xn >= 0.0f) && (xn <= 1.0f) && (yn >= 0.0f) && (yn <= 1.0f);
        int gx = min(max((int)(xn * 127.0f), 0), 127);
        int gy = min(max((int)(yn * 127.0f), 0), 127);
        // cell-major scratch base: (b*HW + cell) * 128
        int cellb = valid ? (((p / 120000) * HW + gy * 128 + gx) << 7) : -1;

        // bases + points for the 4 rows this lane's accumulators cover (rows g+8q)
        int cell_r[4];
        float4 ptq[4];
        #pragma unroll
        for (int q = 0; q < 4; q++) {
            int src = g + 8 * q;
            cell_r[q] = __shfl_sync(0xffffffffu, cellb, src);
            ptq[q].x = __shfl_sync(0xffffffffu, pt.x, src);
            ptq[q].y = __shfl_sync(0xffffffffu, pt.y, src);
            ptq[q].z = __shfl_sync(0xffffffffu, pt.z, src);
            ptq[q].w = __shfl_sync(0xffffffffu, pt.w, src);
        }

        // ---- layer 1: build A1 fp16 fragments directly in registers ----
        uint32_t a1[4][2][4];
        #pragma unroll
        for (int ks = 0; ks < 4; ks++)
            #pragma unroll
            for (int off8 = 0; off8 < 2; off8++) {
                int k0 = ks * 16 + off8 * 8 + cbase;
                float4 w0 = sW1[k0], w1 = sW1[k0 + 1];
                float bb0 = sb1[k0], bb1 = sb1[k0 + 1];
                #pragma unroll
                for (int mb = 0; mb < 2; mb++)
                    #pragma unroll
                    for (int rh = 0; rh < 2; rh++) {
                        float4 q = ptq[2 * mb + rh];
                        float v0 = bb0, v1 = bb1;
                        v0 = fmaf(q.x, w0.x, v0); v0 = fmaf(q.y, w0.y, v0);
                        v0 = fmaf(q.z, w0.z, v0); v0 = fmaf(q.w, w0.w, v0);
                        v1 = fmaf(q.x, w1.x, v1); v1 = fmaf(q.y, w1.y, v1);
                        v1 = fmaf(q.z, w1.z, v1); v1 = fmaf(q.w, w1.w, v1);
                        a1[ks][mb][off8 * 2 + rh] = pack2(fmaxf(v0, 0.0f), fmaxf(v1, 0.0f));
                    }
            }

        // ---- layer 2 + epilogue, ONE 32-col chunk at a time (acc2 = 32 regs) ----
        uint32_t a2[8][2][4];
        #pragma unroll
        for (int nc = 0; nc < 4; nc++) {
            float acc2[2][4][4];
            #pragma unroll
            for (int mb = 0; mb < 2; mb++)
                #pragma unroll
                for (int nt = 0; nt < 4; nt++)
                    #pragma unroll
                    for (int r = 0; r < 4; r++) acc2[mb][nt][r] = 0.0f;

            l2_pass(a1, smb + OFF_W2 + nc * (32 * STR2 * 2), boff2, acc2);

            // bias+relu, convert C frags -> layer-3 A frags (ks3 = nc*2 + sub)
            #pragma unroll
            for (int sub = 0; sub < 2; sub++) {
                const int ks3 = nc * 2 + sub;
                const int ntA = sub * 2;
                const int colA = ks3 * 16 + cbase;
                float bA0 = sb2[colA], bA1 = sb2[colA + 1];
                float bB0 = sb2[colA + 8], bB1 = sb2[colA + 9];
                #pragma unroll
                for (int mb = 0; mb < 2; mb++) {
                    a2[ks3][mb][0] = pack2(fmaxf(acc2[mb][ntA][0] + bA0, 0.0f),
                                           fmaxf(acc2[mb][ntA][1] + bA1, 0.0f));
                    a2[ks3][mb][1] = pack2(fmaxf(acc2[mb][ntA][2] + bA0, 0.0f),
                                           fmaxf(acc2[mb][ntA][3] + bA1, 0.0f));
                    a2[ks3][mb][2] = pack2(fmaxf(acc2[mb][ntA + 1][0] + bB0, 0.0f),
                                           fmaxf(acc2[mb][ntA + 1][1] + bB1, 0.0f));
                    a2[ks3][mb][3] = pack2(fmaxf(acc2[mb][ntA + 1][2] + bB0, 0.0f),
                                           fmaxf(acc2[mb][ntA + 1][3] + bB1, 0.0f));
                }
            }
        }

        // ---- layer 3: [32x128] x [128x128]^T + contiguous scatter-max ----
        #pragma unroll
        for (int nh3 = 0; nh3 < 2; nh3++) {
            float acc3[2][8][4];
            #pragma unroll
            for (int mb = 0; mb < 2; mb++)
                #pragma unroll
                for (int nt = 0; nt < 8; nt++)
                    #pragma unroll
                    for (int r = 0; r < 4; r++) acc3[mb][nt][r] = 0.0f;

            l3_pass(a2, smb + OFF_W3 + nh3 * (64 * STR3 * 2), boff3, acc3);

            // scatter: relu folded into the >0 skip (scratch is zero at entry)
            #pragma unroll
            for (int mb = 0; mb < 2; mb++)
                #pragma unroll
                for (int rp = 0; rp < 2; rp++) {
                    int cb = cell_r[mb * 2 + rp];
                    if (cb >= 0) {
                        int* orow = g_scr + cb;
                        #pragma unroll
                        for (int nt = 0; nt < 8; nt++) {
                            int col = nh3 * 64 + nt * 8 + cbase;
                            float v0 = acc3[mb][nt][2 * rp]     + sb3[col];
                            float v1 = acc3[mb][nt][2 * rp + 1] + sb3[col + 1];
                            if (v0 > 0.0f) atomicMax(orow + col,     __float_as_int(v0));
                            if (v1 > 0.0f) atomicMax(orow + col + 1, __float_as_int(v1));
                        }
                    }
                }
        }
    }
}

// transpose v2: each block handles 32 cells x ALL 128 feats (grid 2048).
// load: 4 float4/thread; store: 4 fully-coalesced float4/thread.
// bank-conflict-free both phases on tile[128][33].
__global__ void __launch_bounds__(256)
transpose_kernel(float* __restrict__ out)
{
    __shared__ float tile[128][33];        // [feat][cell]
    const float* scr = (const float*)g_scr;
    int b  = blockIdx.y;
    int c0 = blockIdx.x * 32;
    int tid = threadIdx.x;                 // 256 threads
    int lane = tid & 31, w = tid >> 5;     // 8 warps

    // load: thread covers cell row cr, float4 cols f4 + 8k
    int cr = tid >> 3, f4 = tid & 7;
    const float* src = scr + ((size_t)(b * HW + c0 + cr)) * 128;
    #pragma unroll
    for (int k = 0; k < 4; k++) {
        float4 v = *(const float4*)(src + (f4 + 8 * k) * 4);
        int f = (f4 + 8 * k) * 4;
        tile[f + 0][cr] = v.x; tile[f + 1][cr] = v.y;
        tile[f + 2][cr] = v.z; tile[f + 3][cr] = v.w;
    }
    __syncthreads();

    // store: warp w covers feat rows w*16 .. w*16+15, 4 rows per pass
    #pragma unroll
    for (int k = 0; k < 4; k++) {
        int f = w * 16 + k * 4 + (lane >> 3);
        int c = (lane & 7) * 4;
        float4 o;
        o.x = tile[f][c + 0]; o.y = tile[f][c + 1];
        o.z = tile[f][c + 2]; o.w = tile[f][c + 3];
        *(float4*)(out + ((size_t)(b * 128 + f)) * HW + c0 + c) = o;
    }
}

extern "C" void kernel_launch(void* const* d_in, const int* in_sizes, int n_in,
                              void* d_out, int out_size)
{
    const float* points = (const float*)d_in[0];
    const float* W1  = (const float*)d_in[1];
    const float* b1  = (const float*)d_in[2];
    const float* g1  = (const float*)d_in[3];
    const float* be1 = (const float*)d_in[4];
    const float* m1  = (const float*)d_in[5];
    const float* v1  = (const float*)d_in[6];
    const float* W2  = (const float*)d_in[7];
    const float* b2  = (const float*)d_in[8];
    const float* g2  = (const float*)d_in[9];
    const float* be2 = (const float*)d_in[10];
    const float* m2  = (const float*)d_in[11];
    const float* v2  = (const float*)d_in[12];
    const float* W3  = (const float*)d_in[13];
    const float* b3  = (const float*)d_in[14];
    const float* g3  = (const float*)d_in[15];
    const float* be3 = (const float*)d_in[16];
    const float* m3  = (const float*)d_in[17];
    const float* v3  = (const float*)d_in[18];

    init_kernel<<<2048, 256>>>(W1, b1, g1, be1, m1, v1,
                               W2, b2, g2, be2, m2, v2,
                               W3, b3, g3, be3, m3, v3);

    cudaFuncSetAttribute(enc_kernel,
                         cudaFuncAttributeMaxDynamicSharedMemorySize, SMEM_SZ);
    enc_kernel<<<444, 128, SMEM_SZ>>>((const float4*)points);

    transpose_kernel<<<dim3(512, 4), dim3(256)>>>((float*)d_out);
}